// round 8
// baseline (speedup 1.0000x reference)
#include <cuda_runtime.h>
#include <cuda_fp16.h>
#include <cstdint>

// Fourier-KAN: out[b,o] = bias[o] + sum_{i,k} cos(k x[b,i]) c0[i,o,k-1] + sin(k x) c1[i,o,k-1]
// B=32768, I=512, O=64, G=8  ->  GEMM M=32768, N=64, K=8192, fp16 features on the fly.
// R8: A fragments computed IN REGISTERS (no A smem traffic at all).
//   - lane j of each quad runs the Chebyshev chain for i-offset j of the quad's rows
//   - 4x4 quad shuffle-transpose redistributes harmonic-pairs to fragment layout
//   - B streamed via 3-stage cp.async ring (only smem user: 40KB/chunk crossbar vs 136KB)
// 4 warps/CTA, 32 rows x 64 cols per warp, MCTA=128, grid=256.

#define NB 32768
#define NI 512
#define NO 64
#define NG 8
#define KTOT 8192
#define MCTA 128
#define KC 64              // 4 i-values * 16 features
#define NCHUNK 128
#define NTHREADS 128
#define BSTAGES 3
#define BBYTES (64 * 128)  // one B chunk: 64 rows x 128B

// repacked coeffs: Wt[o][k], k = i*16 + t*8 + g; t=0: cos freq g+1, t=1: sin freq g+1
__device__ __half g_Wt[NO * KTOT];

// ---------------- helpers ----------------
__device__ __forceinline__ uint32_t smem_u32(const void* p) {
    uint32_t a;
    asm("{ .reg .u64 t; cvta.to.shared.u64 t, %1; cvt.u32.u64 %0, t; }" : "=r"(a) : "l"(p));
    return a;
}

#define SW128(o) ((o) ^ (((o) >> 3) & 0x70))

#define LDSM_X4(r0, r1, r2, r3, addr) \
    asm volatile("ldmatrix.sync.aligned.m8n8.x4.shared.b16 {%0,%1,%2,%3}, [%4];" \
                 : "=r"(r0), "=r"(r1), "=r"(r2), "=r"(r3) : "r"(addr))

#define CP_ASYNC16(dst, src) \
    asm volatile("cp.async.ca.shared.global [%0], [%1], 16;" \
                 :: "r"(dst), "l"(src) : "memory")
#define CP_COMMIT() asm volatile("cp.async.commit_group;" ::: "memory")
#define CP_WAIT1()  asm volatile("cp.async.wait_group 1;" ::: "memory")

__device__ __forceinline__ void mma16816(float* d, const uint32_t* a,
                                         uint32_t b0, uint32_t b1) {
    asm volatile(
        "mma.sync.aligned.m16n8k16.row.col.f32.f16.f16.f32 "
        "{%0,%1,%2,%3}, {%4,%5,%6,%7}, {%8,%9}, {%0,%1,%2,%3};"
        : "+f"(d[0]), "+f"(d[1]), "+f"(d[2]), "+f"(d[3])
        : "r"(a[0]), "r"(a[1]), "r"(a[2]), "r"(a[3]), "r"(b0), "r"(b1));
}

// 4x4 transpose across a lane-quad: v[s] (lane j) -> v'[s] = old v[j] of lane s.
// Stage 1 swaps bit j0<->s0 (bfly 1), stage 2 swaps j1<->s1 (bfly 2).
__device__ __forceinline__ void quad_transpose4(uint32_t v[4], int j) {
    const bool b0 = (j & 1) != 0;
    const bool b1 = (j & 2) != 0;
    uint32_t t0 = b0 ? v[0] : v[1];
    uint32_t t1 = b0 ? v[2] : v[3];
    t0 = __shfl_xor_sync(0xffffffffu, t0, 1);
    t1 = __shfl_xor_sync(0xffffffffu, t1, 1);
    if (b0) { v[0] = t0; v[2] = t1; } else { v[1] = t0; v[3] = t1; }
    uint32_t u0 = b1 ? v[0] : v[2];
    uint32_t u1 = b1 ? v[1] : v[3];
    u0 = __shfl_xor_sync(0xffffffffu, u0, 2);
    u1 = __shfl_xor_sync(0xffffffffu, u1, 2);
    if (b1) { v[0] = u0; v[1] = u1; } else { v[2] = u0; v[3] = u1; }
}

// ---------------- prep: repack coeffs (2,I,O,G) f32 -> Wt[o][k] fp16 ----------------
__global__ void fkan_prep(const float* __restrict__ cf) {
    int idx = blockIdx.x * blockDim.x + threadIdx.x;
    if (idx >= NO * KTOT) return;
    int o = idx >> 13;
    int k = idx & (KTOT - 1);
    int i = k >> 4;
    int f = k & 15;
    int t = f >> 3;               // 0 = cos, 1 = sin
    int g = f & 7;                // freq-1
    float v = cf[(((t * NI) + i) * NO + o) * NG + g];
    g_Wt[o * KTOT + k] = __float2half(v);
}

// ---------------- main fused kernel ----------------
__global__ void __launch_bounds__(NTHREADS)
fkan_main(const float* __restrict__ x, const float* __restrict__ bias,
          float* __restrict__ out) {
    __shared__ __align__(1024) char smem[BSTAGES * BBYTES];
    const uint32_t sbase = smem_u32(smem);

    const int tid = threadIdx.x;
    const int w = tid >> 5;             // 0..3: rows w*32..+31
    const int lane = tid & 31;
    const int q = lane >> 2;
    const int j = lane & 3;

    // ---- x pointers: this lane computes i = 4c + j for 4 row-slots ----
    const int ctaRow = blockIdx.x * MCTA;
    const float* xp[4];
    #pragma unroll
    for (int u = 0; u < 4; ++u) {
        const int roff = (u & 1) * 8 + (u >> 1) * 16;   // q, q+8, q+16, q+24
        xp[u] = x + (size_t)(ctaRow + w * 32 + q + roff) * NI + j;
    }

    // ---- B loader: thread t -> row t>>1, 4 x 16B units at (t&1)*4 ----
    const int bo = tid >> 1;
    const int buh = (tid & 1) << 2;
    const __half* wsrc = g_Wt + bo * KTOT + buh * 8;
    uint32_t b_st[4];
    #pragma unroll
    for (int u = 0; u < 4; ++u)
        b_st[u] = SW128((uint32_t)(bo * 128 + (buh + u) * 16));

    // ---- B ldmatrix lane addrs (same as proven R6 path) ----
    const uint32_t bl = (uint32_t)((lane & 7) + ((lane >> 4) << 3));
    const uint32_t bbo = (uint32_t)(((lane >> 3) & 1) << 4);
    uint32_t b_ls[4];
    #pragma unroll
    for (int t = 0; t < 4; ++t)
        b_ls[t] = SW128((uint32_t)((t * 16 + bl) * 128 + bbo));

    float acc[2][8][4];
    #pragma unroll
    for (int mi = 0; mi < 2; ++mi)
        #pragma unroll
        for (int jj = 0; jj < 8; ++jj)
            #pragma unroll
            for (int qq = 0; qq < 4; ++qq) acc[mi][jj][qq] = 0.0f;

    auto issueB = [&](int c) {
        const uint32_t d0 = sbase + (uint32_t)(c % BSTAGES) * BBYTES;
        const __half* s = wsrc + (size_t)c * KC;
        #pragma unroll
        for (int u = 0; u < 4; ++u)
            CP_ASYNC16(d0 + b_st[u], s + u * 8);
    };

    // ---- prologue ----
    issueB(0); CP_COMMIT();
    issueB(1); CP_COMMIT();
    float xv[4];
    #pragma unroll
    for (int u = 0; u < 4; ++u) xv[u] = *(xp[u]);
    CP_WAIT1();          // chunk-0 B done
    __syncthreads();

    #pragma unroll 1
    for (int c = 0; c < NCHUNK; ++c) {
        // kick B for c+2
        if (c + 2 < NCHUNK) issueB(c + 2);
        CP_COMMIT();

        // prefetch x for c+1 (clamped)
        const int cp = (c + 1 < NCHUNK) ? c + 1 : NCHUNK - 1;
        float xn[4];
        #pragma unroll
        for (int u = 0; u < 4; ++u) xn[u] = *(xp[u] + cp * 4);

        // ---- chains + quad transpose -> A fragments in registers ----
        // TC[u][s]: after transpose, pair j (this lane) of i-offset s, row-slot u.
        uint32_t TC[4][4], TS[4][4];
        #pragma unroll
        for (int u = 0; u < 4; ++u) {
            float s1, c1;
            __sincosf(xv[u], &s1, &c1);
            const float t2 = c1 + c1;
            float ca = c1, sa = s1;
            float cb = fmaf(t2, c1, -1.0f);
            float sb = t2 * s1;
            __half2 h;
            h = __floats2half2_rn(ca, cb); TC[u][0] = *(uint32_t*)&h;
            h = __floats2half2_rn(sa, sb); TS[u][0] = *(uint32_t*)&h;
            #pragma unroll
            for (int p = 1; p < 4; ++p) {
                const float c_odd = fmaf(t2, cb, -ca);
                const float s_odd = fmaf(t2, sb, -sa);
                const float c_evn = fmaf(t2, c_odd, -cb);
                const float s_evn = fmaf(t2, s_odd, -sb);
                ca = c_odd; sa = s_odd; cb = c_evn; sb = s_evn;
                h = __floats2half2_rn(c_odd, c_evn); TC[u][p] = *(uint32_t*)&h;
                h = __floats2half2_rn(s_odd, s_evn); TS[u][p] = *(uint32_t*)&h;
            }
            quad_transpose4(TC[u], j);
            quad_transpose4(TS[u], j);
        }

        // ---- mma over 4 k16-steps from B smem + register A ----
        const uint32_t bB = sbase + (uint32_t)(c % BSTAGES) * BBYTES;
        #pragma unroll
        for (int ks = 0; ks < 4; ++ks) {
            const uint32_t kx = (uint32_t)(ks << 5);
            uint32_t b[16];
            #pragma unroll
            for (int t = 0; t < 4; ++t)
                LDSM_X4(b[4 * t], b[4 * t + 1], b[4 * t + 2], b[4 * t + 3],
                        bB + (b_ls[t] ^ kx));
            const uint32_t a0[4] = {TC[0][ks], TC[1][ks], TS[0][ks], TS[1][ks]};
            const uint32_t a1[4] = {TC[2][ks], TC[3][ks], TS[2][ks], TS[3][ks]};
            #pragma unroll
            for (int jj = 0; jj < 8; ++jj) {
                const int t = jj >> 1;
                const int hi = (jj & 1) << 1;
                mma16816(acc[0][jj], a0, b[4 * t + hi], b[4 * t + hi + 1]);
                mma16816(acc[1][jj], a1, b[4 * t + hi], b[4 * t + hi + 1]);
            }
        }

        #pragma unroll
        for (int u = 0; u < 4; ++u) xv[u] = xn[u];
        CP_WAIT1();          // B for c+1 complete (this thread)
        __syncthreads();     // publish across threads; all reads of buf c done
    }

    // ---- epilogue: acc (+bias) -> out ----
    const int gr = lane >> 2;
    const int gc = (lane & 3) << 1;
    #pragma unroll
    for (int mi = 0; mi < 2; ++mi) {
        const int row0 = ctaRow + w * 32 + mi * 16 + gr;
        #pragma unroll
        for (int jj = 0; jj < 8; ++jj) {
            const int col = jj * 8 + gc;
            float2 bb2 = *(const float2*)(bias + col);
            float2 v0, v1;
            v0.x = acc[mi][jj][0] + bb2.x; v0.y = acc[mi][jj][1] + bb2.y;
            v1.x = acc[mi][jj][2] + bb2.x; v1.y = acc[mi][jj][3] + bb2.y;
            *(float2*)(out + (size_t)row0 * NO + col) = v0;
            *(float2*)(out + (size_t)(row0 + 8) * NO + col) = v1;
        }
    }
}

// ---------------- launch ----------------
extern "C" void kernel_launch(void* const* d_in, const int* in_sizes, int n_in,
                              void* d_out, int out_size) {
    const float* x    = (const float*)d_in[0];
    const float* cf   = (const float*)d_in[1];
    const float* bias = (const float*)d_in[2];
    float* out        = (float*)d_out;

    fkan_prep<<<(NO * KTOT + 255) / 256, 256>>>(cf);
    fkan_main<<<NB / MCTA, NTHREADS>>>(x, bias, out);
}